// round 7
// baseline (speedup 1.0000x reference)
#include <cuda_runtime.h>
#include <cstdint>

#define HDIM 4096
#define TPB  256
#define ROWS_PER_CTA 4
#define V4 4   // 4 float4 per thread per row (16 floats)

__global__ __launch_bounds__(TPB)
void quant_int4_kernel(const float* __restrict__ x,
                       float* __restrict__ packed_out,   // packed int8 VALUES as fp32
                       float* __restrict__ scales_out)
{
    const int t        = threadIdx.x;
    const int row0     = blockIdx.x * ROWS_PER_CTA;
    const int lane     = t & 31;
    const int warp     = t >> 5;

    __shared__ float smax[2][TPB / 32];   // double-buffered: 1 barrier/row

    // Thread t owns 16 contiguous floats [t*16, t*16+16) of each row,
    // and the 8 contiguous output floats [t*8, t*8+8).
    const float* __restrict__ xbase = x + (size_t)row0 * HDIM + t * 16;

    // ---- prologue: load row 0 ----
    float4 cur[V4];
#pragma unroll
    for (int i = 0; i < V4; i++)
        cur[i] = reinterpret_cast<const float4*>(xbase)[i];

#pragma unroll
    for (int r = 0; r < ROWS_PER_CTA; r++) {
        const int row = row0 + r;

        // ---- issue next row's loads BEFORE this row's barrier ----
        float4 nxt[V4];
        if (r + 1 < ROWS_PER_CTA) {
            const float4* np =
                reinterpret_cast<const float4*>(xbase + (size_t)(r + 1) * HDIM);
#pragma unroll
            for (int i = 0; i < V4; i++) nxt[i] = np[i];
        }

        // ---- absmax over cur ----
        float amax = 0.0f;
#pragma unroll
        for (int i = 0; i < V4; i++)
            amax = fmaxf(amax, fmaxf(fmaxf(fabsf(cur[i].x), fabsf(cur[i].y)),
                                     fmaxf(fabsf(cur[i].z), fabsf(cur[i].w))));
#pragma unroll
        for (int o = 16; o > 0; o >>= 1)
            amax = fmaxf(amax, __shfl_xor_sync(0xffffffffu, amax, o));

        const int buf = r & 1;
        if (lane == 0) smax[buf][warp] = amax;
        __syncthreads();

        float rmax = smax[buf][0];
#pragma unroll
        for (int w = 1; w < TPB / 32; w++) rmax = fmaxf(rmax, smax[buf][w]);

        const float scale = fmaxf(rmax * (0.9f / 7.0f), 1e-8f);
        const float inv   = 1.0f / scale;
        if (t == 0) scales_out[row] = scale;

        // ---- quantize + pack: 16 floats -> 8 bytes-as-fp32 -> two float4 stores ----
        float4* __restrict__ orow =
            reinterpret_cast<float4*>(packed_out + (size_t)row * (HDIM / 2) + t * 8);

#pragma unroll
        for (int h = 0; h < 2; h++) {          // two float4 outputs
            float4 o;
            float* op = &o.x;
#pragma unroll
            for (int j = 0; j < 4; j++) {
                const float4& s = cur[h * 2 + (j >> 1)];
                float e0 = (j & 1) ? s.z : s.x;
                float e1 = (j & 1) ? s.w : s.y;
                int q0 = __float2int_rn(e0 * inv);
                int q1 = __float2int_rn(e1 * inv);
                q0 = max(-8, min(7, q0));
                q1 = max(-8, min(7, q1));
                // elem0 -> low nibble, elem1 -> high nibble; byte is SIGNED int8
                op[j] = (float)(int8_t)(uint8_t)((q0 & 0xF) | ((q1 & 0xF) << 4));
            }
            orow[h] = o;
        }

        // ---- rotate pipeline ----
#pragma unroll
        for (int i = 0; i < V4; i++) cur[i] = nxt[i];
    }
}

extern "C" void kernel_launch(void* const* d_in, const int* in_sizes, int n_in,
                              void* d_out, int out_size)
{
    const float* x = (const float*)d_in[0];
    const int n_elems = in_sizes[0];              // 4*2048*4096
    const int rows    = n_elems / HDIM;           // 8192

    float* packed = (float*)d_out;                         // [rows, 2048] as fp32
    float* scales = (float*)d_out + (size_t)rows * (HDIM / 2);  // [rows] fp32

    quant_int4_kernel<<<rows / ROWS_PER_CTA, TPB>>>(x, packed, scales);
}

// round 8
// speedup vs baseline: 1.0588x; 1.0588x over previous
#include <cuda_runtime.h>
#include <cstdint>

#define HDIM 4096
#define TPB  256
#define NCTAS (148 * 8)   // persistent: one full wave, grid-stride over rows

__global__ __launch_bounds__(TPB, 8)
void quant_int4_kernel(const float* __restrict__ x,
                       float* __restrict__ packed_out,   // packed int8 VALUES as fp32
                       float* __restrict__ scales_out,
                       int rows)
{
    const int t    = threadIdx.x;
    const int lane = t & 31;
    const int warp = t >> 5;

    __shared__ float smax[2][TPB / 32];   // parity-buffered: 1 barrier per row

    int it = 0;
    for (int row = blockIdx.x; row < rows; row += NCTAS, it ^= 1) {
        const float4* __restrict__ xrow =
            reinterpret_cast<const float4*>(x + (size_t)row * HDIM);

        // ---- pass 1: 4 x 16B loads per thread, absmax in regs ----
        float4 v[4];
        float amax = 0.0f;
#pragma unroll
        for (int i = 0; i < 4; i++) {
            v[i] = xrow[i * TPB + t];
            amax = fmaxf(amax, fmaxf(fmaxf(fabsf(v[i].x), fabsf(v[i].y)),
                                     fmaxf(fabsf(v[i].z), fabsf(v[i].w))));
        }

        // ---- warp reduction ----
#pragma unroll
        for (int o = 16; o > 0; o >>= 1)
            amax = fmaxf(amax, __shfl_xor_sync(0xffffffffu, amax, o));

        // ---- cross-warp reduction, single barrier (parity buffer) ----
        if (lane == 0) smax[it][warp] = amax;
        __syncthreads();

        float rmax = smax[it][0];
#pragma unroll
        for (int w = 1; w < TPB / 32; w++) rmax = fmaxf(rmax, smax[it][w]);

        const float scale = fmaxf(rmax * (0.9f / 7.0f), 1e-8f);
        const float inv   = 1.0f / scale;
        if (t == 0) scales_out[row] = scale;

        // ---- pass 2: quantize from regs, pack 2 nibbles -> int8 value -> fp32 ----
        float2* __restrict__ orow =
            reinterpret_cast<float2*>(packed_out + (size_t)row * (HDIM / 2));

#pragma unroll
        for (int i = 0; i < 4; i++) {
            int q0 = __float2int_rn(v[i].x * inv);
            int q1 = __float2int_rn(v[i].y * inv);
            int q2 = __float2int_rn(v[i].z * inv);
            int q3 = __float2int_rn(v[i].w * inv);
            q0 = max(-8, min(7, q0));
            q1 = max(-8, min(7, q1));
            q2 = max(-8, min(7, q2));
            q3 = max(-8, min(7, q3));
            // elem0 -> low nibble, elem1 -> high nibble; byte is SIGNED int8
            float2 o;
            o.x = (float)(int8_t)(uint8_t)((q0 & 0xF) | ((q1 & 0xF) << 4));
            o.y = (float)(int8_t)(uint8_t)((q2 & 0xF) | ((q3 & 0xF) << 4));
            orow[i * TPB + t] = o;
        }
    }
}

extern "C" void kernel_launch(void* const* d_in, const int* in_sizes, int n_in,
                              void* d_out, int out_size)
{
    const float* x = (const float*)d_in[0];
    const int n_elems = in_sizes[0];              // 4*2048*4096
    const int rows    = n_elems / HDIM;           // 8192

    float* packed = (float*)d_out;                         // [rows, 2048] as fp32
    float* scales = (float*)d_out + (size_t)rows * (HDIM / 2);  // [rows] fp32

    quant_int4_kernel<<<NCTAS, TPB>>>(x, packed, scales, rows);
}

// round 9
// speedup vs baseline: 1.1260x; 1.0635x over previous
#include <cuda_runtime.h>
#include <cstdint>

#define HDIM 4096
#define TPB  256

__global__ __launch_bounds__(TPB, 8)
void quant_int4_kernel(const float* __restrict__ x,
                       float* __restrict__ packed_out,   // packed int8 VALUES as fp32
                       float* __restrict__ scales_out)
{
    const int row  = blockIdx.x;
    const int t    = threadIdx.x;
    const int lane = t & 31;
    const int warp = t >> 5;

    const float4* __restrict__ xrow =
        reinterpret_cast<const float4*>(x + (size_t)row * HDIM);

    // ---- pass 1: 4 x 16B loads per thread (16 floats in regs), absmax ----
    float4 v[4];
    float amax = 0.0f;
#pragma unroll
    for (int i = 0; i < 4; i++) {
        v[i] = xrow[i * TPB + t];
        amax = fmaxf(amax, fmaxf(fmaxf(fabsf(v[i].x), fabsf(v[i].y)),
                                 fmaxf(fabsf(v[i].z), fabsf(v[i].w))));
    }

    // ---- warp reduction: single REDUX on bit pattern (valid for x >= 0) ----
    unsigned int ubits = __reduce_max_sync(0xffffffffu, __float_as_uint(amax));

    // ---- cross-warp reduction (8 warps) ----
    __shared__ unsigned int smax[TPB / 32];
    if (lane == 0) smax[warp] = ubits;
    __syncthreads();

    unsigned int rbits = smax[0];
#pragma unroll
    for (int w = 1; w < TPB / 32; w++) rbits = max(rbits, smax[w]);
    const float rmax = __uint_as_float(rbits);

    const float scale = fmaxf(rmax * (0.9f / 7.0f), 1e-8f);
    const float inv   = 1.0f / scale;
    if (t == 0) scales_out[row] = scale;

    // ---- pass 2: quantize from regs; 16 floats -> 8 bytes-as-fp32 -> 2 float4 stores ----
    // Thread t's inputs v[0..3] are at float4-index {0,256,512,768}+t of the row;
    // corresponding outputs are float2-index {0,256,512,768}+t -> pair (v[2h],v[2h+1])
    // forms one float4 output at float4-index h*256 + ... NOT contiguous. Keep the
    // same strided mapping but pack two float2 results from v[2h], v[2h+1]? They sit
    // 256*2 floats apart in the output -- not mergeable. So: remap ownership so each
    // thread's two load pairs are output-contiguous: v[i] at index i*TPB+t maps to
    // output float2 at i*TPB+t. Merge (i=0,i=1)? indices TPB apart. Not contiguous.
    // => keep float2 stores (already perfectly coalesced per warp).
    float2* __restrict__ orow =
        reinterpret_cast<float2*>(packed_out + (size_t)row * (HDIM / 2));

#pragma unroll
    for (int i = 0; i < 4; i++) {
        int q0 = __float2int_rn(v[i].x * inv);
        int q1 = __float2int_rn(v[i].y * inv);
        int q2 = __float2int_rn(v[i].z * inv);
        int q3 = __float2int_rn(v[i].w * inv);
        q0 = max(-8, min(7, q0));
        q1 = max(-8, min(7, q1));
        q2 = max(-8, min(7, q2));
        q3 = max(-8, min(7, q3));
        // elem0 -> low nibble, elem1 -> high nibble; byte is SIGNED int8
        float2 o;
        o.x = (float)(int8_t)(uint8_t)((q0 & 0xF) | ((q1 & 0xF) << 4));
        o.y = (float)(int8_t)(uint8_t)((q2 & 0xF) | ((q3 & 0xF) << 4));
        orow[i * TPB + t] = o;
    }
}

extern "C" void kernel_launch(void* const* d_in, const int* in_sizes, int n_in,
                              void* d_out, int out_size)
{
    const float* x = (const float*)d_in[0];
    const int n_elems = in_sizes[0];              // 4*2048*4096
    const int rows    = n_elems / HDIM;           // 8192

    float* packed = (float*)d_out;                         // [rows, 2048] as fp32
    float* scales = (float*)d_out + (size_t)rows * (HDIM / 2);  // [rows] fp32

    quant_int4_kernel<<<rows, TPB>>>(x, packed, scales);
}